// round 8
// baseline (speedup 1.0000x reference)
#include <cuda_runtime.h>
#include <math.h>

#define NG  3200   // graphs = B*L
#define E   50     // nodes per graph
#define D   100    // embedding dim
#define H   100    // head dim
#define NP  128    // padded column count for weight tiles
#define KA  104    // padded K for k_u (multiple of 8)

// Scratch (no allocation allowed in kernel_launch)
__device__ __align__(16) float g_Ap[KA * NP];     // padded A (rows 100..103 zero)
__device__ __align__(16) float g_cp[NP];          // padded Wk @ bq
__device__ __align__(16) float g_bp[NP];          // padded bv + bs
__device__ __align__(16) float g_Wcp[2 * D * NP]; // padded [Wv ; Ws]
__device__ __align__(16) float g_U[NG * D];       // per-graph u
__device__ __align__(16) float g_wx[NG * 2 * D];  // per-graph packed [w(100) | x0(100)]

// ---------------------------------------------------------------------------
// K1: precompute padded A, c, bvs, Wc.  grid = 300 x 128 threads.
//  blocks 0..99  : stage Wk in smem (coalesced, pad-101), A row e = b.
//                  block 0 additionally: c, bvs, zero A pad rows.
//  blocks 100..299: Wc row k = b-100 (zero-padded copy).
// ---------------------------------------------------------------------------
__global__ void k_pre(const float* __restrict__ Wq, const float* __restrict__ bq,
                      const float* __restrict__ Wk,
                      const float* __restrict__ Wv, const float* __restrict__ bv,
                      const float* __restrict__ Ws, const float* __restrict__ bs) {
    int b = blockIdx.x, t = threadIdx.x;
    if (b < D) {
        __shared__ float wk[D * 101];   // 40.4KB, pad-101 -> conflict-free rows
        __shared__ float wq[H];
        __shared__ float bqs[H];
        if (t < H) wq[t] = Wq[b * H + t];
        if (b == 0) {
            if (t < H) bqs[t] = bq[t];
            // zero A pad rows early (each element written exactly once)
            for (int i = t; i < (KA - D) * NP; i += 128) g_Ap[D * NP + i] = 0.f;
        }
        for (int i = t; i < D * H; i += 128) {
            int r = i / H, cc = i - r * H;
            wk[r * 101 + cc] = Wk[i];
        }
        __syncthreads();
        {
            float acc = 0.f;
            if (t < D) {
                #pragma unroll 4
                for (int h = 0; h < H; ++h) acc = fmaf(wk[t * 101 + h], wq[h], acc);
            }
            g_Ap[b * NP + t] = acc;     // t in [100,128) writes 0 (pad)
        }
        if (b == 0) {
            float c = 0.f, bb = 0.f;
            if (t < D) {
                #pragma unroll 4
                for (int h = 0; h < H; ++h) c = fmaf(wk[t * 101 + h], bqs[h], c);
                bb = bv[t] + bs[t];
            }
            g_cp[t] = c;
            g_bp[t] = bb;
        }
    } else {
        int k = b - D;                   // 0..199
        float v = 0.f;
        if (t < H) v = (k < D) ? Wv[k * H + t] : Ws[(k - D) * H + t];
        g_Wcp[k * NP + t] = v;
    }
}

// ---------------------------------------------------------------------------
// K2: U[g] = c + A x0[g].  grid=400, 256 thr, 8 graphs/CTA.
// warp = 4 graphs x 32 cols.  8-deep register prefetch over padded K=104.
// ---------------------------------------------------------------------------
__global__ __launch_bounds__(256, 2) void k_u(const int* __restrict__ nid,
                                              const float* __restrict__ emb) {
    __shared__ float xs[8][KA];
    __shared__ int ids[8];
    int tid = threadIdx.x, warp = tid >> 5, lane = tid & 31;
    int gbase = blockIdx.x * 8;

    if (tid < 8) ids[tid] = nid[(gbase + tid) * E];
    __syncthreads();
    if (tid < 8 * (D / 4)) {                 // 200 float4, coalesced per row
        int r = tid / 25, c = tid % 25;
        reinterpret_cast<float4*>(&xs[r][0])[c] =
            reinterpret_cast<const float4*>(emb)[ids[r] * (D / 4) + c];
    }
    if (tid < 8 * (KA - D)) xs[tid >> 2][D + (tid & 3)] = 0.f;   // zero pad
    __syncthreads();

    int gg = (warp >> 2) * 4, ct = warp & 3;
    int gl = lane >> 3,       hg = lane & 7;
    int h0 = ct * 32 + hg * 4;
    const float* xr = xs[gg + gl];
    const float* wp = &g_Ap[h0];

    float4 acc = *reinterpret_cast<const float4*>(&g_cp[h0]);
    #pragma unroll
    for (int kb = 0; kb < KA; kb += 8) {
        float4 w[8];
        #pragma unroll
        for (int i = 0; i < 8; ++i)
            w[i] = *reinterpret_cast<const float4*>(&wp[(kb + i) * NP]);
        float4 xa = *reinterpret_cast<const float4*>(&xr[kb]);
        float4 xb = *reinterpret_cast<const float4*>(&xr[kb + 4]);
        float xv[8] = {xa.x, xa.y, xa.z, xa.w, xb.x, xb.y, xb.z, xb.w};
        #pragma unroll
        for (int i = 0; i < 8; ++i) {
            acc.x = fmaf(xv[i], w[i].x, acc.x);
            acc.y = fmaf(xv[i], w[i].y, acc.y);
            acc.z = fmaf(xv[i], w[i].z, acc.z);
            acc.w = fmaf(xv[i], w[i].w, acc.w);
        }
    }
    if (h0 < H)
        *reinterpret_cast<float4*>(&g_U[(gbase + gg + gl) * D + h0]) = acc;
}

// ---------------------------------------------------------------------------
// K3: per-graph attention, parallel ballot compaction. 1 CTA/graph, 128 thr.
// ---------------------------------------------------------------------------
__global__ __launch_bounds__(128) void k_attn(const int* __restrict__ nid,
                                              const int* __restrict__ adj,
                                              const float* __restrict__ emb) {
    constexpr int LD = 101;
    __shared__ float X[E * LD];
    __shared__ float u_s[D];
    __shared__ float sc[E];
    __shared__ float ps[E];
    __shared__ int ids[E];
    __shared__ unsigned bal[2];
    __shared__ int cnt_s;

    int g = blockIdx.x, tid = threadIdx.x;
    int warp = tid >> 5, lane = tid & 31;

    int myid = 0, m = 0;
    if (tid < E) {
        myid = nid[g * E + tid];
        m    = adj[g * (E * E) + tid * E];   // edge j -> node 0
    }
    if (tid < D) u_s[tid] = g_U[g * D + tid];

    unsigned bw = __ballot_sync(0xffffffffu, m != 0);
    if (warp < 2 && lane == 0) bal[warp] = bw;
    __syncthreads();
    unsigned b0 = bal[0], b1 = bal[1];
    int cnt = __popc(b0) + __popc(b1);
    if (tid == 0) cnt_s = cnt;
    if (tid < E && m) {
        int pos = __popc((warp ? b0 : 0u)) +
                  __popc((warp ? b1 : b0) & ((1u << lane) - 1u));
        ids[pos] = myid;
    }
    __syncthreads();
    cnt = cnt_s;

    for (int q = tid; q < cnt * (D / 4); q += 128) {
        int r = q / 25, cc = q % 25;
        float4 v = reinterpret_cast<const float4*>(emb)[ids[r] * (D / 4) + cc];
        float* dst = &X[r * LD + cc * 4];
        dst[0] = v.x; dst[1] = v.y; dst[2] = v.z; dst[3] = v.w;
    }
    __syncthreads();

    if (tid < cnt) {
        const float* xr = &X[tid * LD];
        float s0 = 0.f, s1 = 0.f;
        #pragma unroll 10
        for (int d2 = 0; d2 < D; d2 += 2) {
            s0 = fmaf(xr[d2],     u_s[d2],     s0);
            s1 = fmaf(xr[d2 + 1], u_s[d2 + 1], s1);
        }
        sc[tid] = (s0 + s1) * 0.1f;          // /sqrt(H)
    }
    __syncthreads();

    float mx = -1e30f;
    for (int j = 0; j < cnt; ++j) mx = fmaxf(mx, sc[j]);
    if (tid < cnt) ps[tid] = __expf(sc[tid] - mx);
    __syncthreads();

    float S = 0.f;
    for (int j = 0; j < cnt; ++j) S += ps[j];
    float inv = 1.0f / S;

    if (tid < D) {
        float w = 0.f;
        for (int j = 0; j < cnt; ++j) w = fmaf(ps[j], X[j * LD + tid], w);
        g_wx[g * (2 * D) + tid]     = w * inv;
        g_wx[g * (2 * D) + D + tid] = X[tid];   // compact row 0 = x0
    }
}

// ---------------------------------------------------------------------------
// K4: out[g] = bvs + [w|x0] @ [Wv;Ws].  grid=400, 256 thr, K=200.
// warp = 4 graphs x 32 cols.  8-deep register prefetch (25 blocks).
// ---------------------------------------------------------------------------
__global__ __launch_bounds__(256, 2) void k_out(float* __restrict__ out) {
    __shared__ float xs[8][2 * D];
    int tid = threadIdx.x, warp = tid >> 5, lane = tid & 31;
    int gbase = blockIdx.x * 8;

    for (int q = tid; q < 8 * (2 * D / 4); q += 256) {   // 400 float4, coalesced
        int r = q / 50, c = q % 50;
        reinterpret_cast<float4*>(&xs[r][0])[c] =
            reinterpret_cast<const float4*>(g_wx)[(gbase + r) * (2 * D / 4) + c];
    }
    __syncthreads();

    int gg = (warp >> 2) * 4, ct = warp & 3;
    int gl = lane >> 3,       hg = lane & 7;
    int h0 = ct * 32 + hg * 4;
    const float* xr = xs[gg + gl];
    const float* wp = &g_Wcp[h0];

    float4 acc = *reinterpret_cast<const float4*>(&g_bp[h0]);
    #pragma unroll
    for (int kb = 0; kb < 2 * D; kb += 8) {
        float4 w[8];
        #pragma unroll
        for (int i = 0; i < 8; ++i)
            w[i] = *reinterpret_cast<const float4*>(&wp[(kb + i) * NP]);
        float4 xa = *reinterpret_cast<const float4*>(&xr[kb]);
        float4 xb = *reinterpret_cast<const float4*>(&xr[kb + 4]);
        float xv[8] = {xa.x, xa.y, xa.z, xa.w, xb.x, xb.y, xb.z, xb.w};
        #pragma unroll
        for (int i = 0; i < 8; ++i) {
            acc.x = fmaf(xv[i], w[i].x, acc.x);
            acc.y = fmaf(xv[i], w[i].y, acc.y);
            acc.z = fmaf(xv[i], w[i].z, acc.z);
            acc.w = fmaf(xv[i], w[i].w, acc.w);
        }
    }
    if (h0 < H)
        *reinterpret_cast<float4*>(&out[(gbase + gg + gl) * H + h0]) = acc;
}

// ---------------------------------------------------------------------------
extern "C" void kernel_launch(void* const* d_in, const int* in_sizes, int n_in,
                              void* d_out, int out_size) {
    const int*   nid = (const int*)d_in[0];
    const int*   adj = (const int*)d_in[1];
    const float* emb = (const float*)d_in[2];
    const float* Wq  = (const float*)d_in[3];
    const float* bq  = (const float*)d_in[4];
    const float* Wk  = (const float*)d_in[5];
    // d_in[6] = bk: cancels in softmax (constant per-row shift)
    const float* Wv  = (const float*)d_in[7];
    const float* bv  = (const float*)d_in[8];
    const float* Ws  = (const float*)d_in[9];
    const float* bs  = (const float*)d_in[10];
    float* out = (float*)d_out;

    k_pre<<<3 * D, 128>>>(Wq, bq, Wk, Wv, bv, Ws, bs);
    k_u<<<NG / 8, 256>>>(nid, emb);
    k_attn<<<NG, 128>>>(nid, adj, emb);
    k_out<<<NG / 8, 256>>>(out);
}

// round 9
// speedup vs baseline: 3.4039x; 3.4039x over previous
#include <cuda_runtime.h>
#include <math.h>

#define NG  3200   // graphs = B*L
#define E   50     // nodes per graph
#define D   100    // embedding dim
#define H   100    // head dim
#define NP  128    // padded column count for weight tiles

// Scratch (no allocation allowed in kernel_launch)
__device__ __align__(16) float g_Ap[D * NP];      // padded A: u[d]=sum_e x0[e]*g_Ap[e*NP+d]
__device__ __align__(16) float g_cp[NP];          // padded Wk @ bq
__device__ __align__(16) float g_bp[NP];          // padded bv + bs
__device__ __align__(16) float g_Wcp[2 * D * NP]; // padded [Wv ; Ws]
__device__ __align__(16) float g_U[NG * D];       // per-graph u
__device__ __align__(16) float g_wx[NG * 2 * D];  // per-graph packed [w(100) | x0(100)]

// ---------------------------------------------------------------------------
// K1: precompute padded A, c, bvs, Wc.  grid = 300 x 128 threads.
//  blocks 0..99  : stage Wk in smem (coalesced, pad-101), A row e = b.
//                  block 0 additionally: c, bvs.
//  blocks 100..299: Wc row k = b-100 (zero-padded copy).
// ---------------------------------------------------------------------------
__global__ void k_pre(const float* __restrict__ Wq, const float* __restrict__ bq,
                      const float* __restrict__ Wk,
                      const float* __restrict__ Wv, const float* __restrict__ bv,
                      const float* __restrict__ Ws, const float* __restrict__ bs) {
    int b = blockIdx.x, t = threadIdx.x;
    if (b < D) {
        __shared__ float wk[D * 101];   // 40.4KB, pad-101 -> conflict-free rows
        __shared__ float wq[H];
        __shared__ float bqs[H];
        if (t < H) wq[t] = Wq[b * H + t];
        if (b == 0 && t < H) bqs[t] = bq[t];
        for (int i = t; i < D * H; i += 128) {
            int r = i / H, cc = i - r * H;
            wk[r * 101 + cc] = Wk[i];
        }
        __syncthreads();
        {
            float acc = 0.f;
            if (t < D) {
                #pragma unroll 4
                for (int h = 0; h < H; ++h) acc = fmaf(wk[t * 101 + h], wq[h], acc);
            }
            g_Ap[b * NP + t] = acc;     // t in [100,128) writes 0 (pad)
        }
        if (b == 0) {
            float c = 0.f, bb = 0.f;
            if (t < D) {
                #pragma unroll 4
                for (int h = 0; h < H; ++h) c = fmaf(wk[t * 101 + h], bqs[h], c);
                bb = bv[t] + bs[t];
            }
            g_cp[t] = c;
            g_bp[t] = bb;
        }
    } else {
        int k = b - D;                   // 0..199
        float v = 0.f;
        if (t < H) v = (k < D) ? Wv[k * H + t] : Ws[(k - D) * H + t];
        g_Wcp[k * NP + t] = v;
    }
}

// ---------------------------------------------------------------------------
// K2: U[g] = c + A x0[g].  CTA = 32 graphs x 32 cols; grid = 100 x 4 = 400.
// A slice [100][32] + x tile [32][100] staged in smem (25.6KB total).
// Inner loop pure smem: conflict-free LDS.128 (weights) + broadcast LDS.32 (x).
// ---------------------------------------------------------------------------
__global__ __launch_bounds__(256) void k_u(const int* __restrict__ nid,
                                           const float* __restrict__ emb) {
    __shared__ float As[D * 32];    // 12.8KB  [k][c]
    __shared__ float xs[32 * D];    // 12.8KB  [g][k]
    __shared__ int ids[32];

    int tid = threadIdx.x;
    int bt  = blockIdx.x;
    int gt  = bt >> 2, ct = bt & 3;
    int gbase = gt * 32;
    int cbase = ct * 32;

    for (int i = tid; i < D * 32; i += 256)
        As[i] = g_Ap[(i >> 5) * NP + cbase + (i & 31)];
    if (tid < 32) ids[tid] = nid[(gbase + tid) * E];
    __syncthreads();
    for (int q = tid; q < 32 * (D / 4); q += 256) {      // 800 float4
        int r = q / 25, c = q % 25;
        reinterpret_cast<float4*>(&xs[r * D])[c] =
            reinterpret_cast<const float4*>(emb)[ids[r] * (D / 4) + c];
    }
    __syncthreads();

    int gl = tid >> 3, hq = tid & 7;
    int h0 = hq * 4;
    int hglob = cbase + h0;
    const float* xr = &xs[gl * D];

    float4 acc = *reinterpret_cast<const float4*>(&g_cp[hglob]);
    #pragma unroll 4
    for (int k = 0; k < D; ++k) {
        float  xv = xr[k];                                    // 4-addr bcast
        float4 w  = *reinterpret_cast<const float4*>(&As[k * 32 + h0]);
        acc.x = fmaf(xv, w.x, acc.x); acc.y = fmaf(xv, w.y, acc.y);
        acc.z = fmaf(xv, w.z, acc.z); acc.w = fmaf(xv, w.w, acc.w);
    }
    if (hglob < H)
        *reinterpret_cast<float4*>(&g_U[(gbase + gl) * D + hglob]) = acc;
}

// ---------------------------------------------------------------------------
// K3: per-graph attention, parallel ballot compaction. 1 CTA/graph, 128 thr.
// Rows with adj[g][j][0]==0 dropped entirely; node-0 self-loop guaranteed.
// Writes packed g_wx[g] = [w | x0].
// ---------------------------------------------------------------------------
__global__ __launch_bounds__(128) void k_attn(const int* __restrict__ nid,
                                              const int* __restrict__ adj,
                                              const float* __restrict__ emb) {
    constexpr int LD = 101;
    __shared__ float X[E * LD];
    __shared__ float u_s[D];
    __shared__ float sc[E];
    __shared__ float ps[E];
    __shared__ int ids[E];
    __shared__ unsigned bal[2];
    __shared__ int cnt_s;

    int g = blockIdx.x, tid = threadIdx.x;
    int warp = tid >> 5, lane = tid & 31;

    int myid = 0, m = 0;
    if (tid < E) {
        myid = nid[g * E + tid];
        m    = adj[g * (E * E) + tid * E];   // edge j -> node 0
    }
    if (tid < D) u_s[tid] = g_U[g * D + tid];

    unsigned bw = __ballot_sync(0xffffffffu, m != 0);
    if (warp < 2 && lane == 0) bal[warp] = bw;
    __syncthreads();
    unsigned b0 = bal[0], b1 = bal[1];
    int cnt = __popc(b0) + __popc(b1);
    if (tid == 0) cnt_s = cnt;
    if (tid < E && m) {
        int pos = __popc((warp ? b0 : 0u)) +
                  __popc((warp ? b1 : b0) & ((1u << lane) - 1u));
        ids[pos] = myid;
    }
    __syncthreads();
    cnt = cnt_s;

    for (int q = tid; q < cnt * (D / 4); q += 128) {
        int r = q / 25, cc = q % 25;
        float4 v = reinterpret_cast<const float4*>(emb)[ids[r] * (D / 4) + cc];
        float* dst = &X[r * LD + cc * 4];
        dst[0] = v.x; dst[1] = v.y; dst[2] = v.z; dst[3] = v.w;
    }
    __syncthreads();

    if (tid < cnt) {
        const float* xr = &X[tid * LD];
        float s0 = 0.f, s1 = 0.f;
        #pragma unroll 10
        for (int d2 = 0; d2 < D; d2 += 2) {
            s0 = fmaf(xr[d2],     u_s[d2],     s0);
            s1 = fmaf(xr[d2 + 1], u_s[d2 + 1], s1);
        }
        sc[tid] = (s0 + s1) * 0.1f;          // /sqrt(H)
    }
    __syncthreads();

    float mx = -1e30f;
    for (int j = 0; j < cnt; ++j) mx = fmaxf(mx, sc[j]);
    if (tid < cnt) ps[tid] = __expf(sc[tid] - mx);
    __syncthreads();

    float S = 0.f;
    for (int j = 0; j < cnt; ++j) S += ps[j];
    float inv = 1.0f / S;

    if (tid < D) {
        float w = 0.f;
        for (int j = 0; j < cnt; ++j) w = fmaf(ps[j], X[j * LD + tid], w);
        g_wx[g * (2 * D) + tid]     = w * inv;
        g_wx[g * (2 * D) + D + tid] = X[tid];   // compact row 0 = x0
    }
}

// ---------------------------------------------------------------------------
// K4: out[g] = bvs + [w|x0] @ [Wv;Ws].  CTA = 32 graphs x 32 cols; grid=400.
// Wc slice [200][32] + wx tile [32][200] in dynamic smem (51.2KB).
// ---------------------------------------------------------------------------
__global__ __launch_bounds__(256) void k_out(float* __restrict__ out) {
    extern __shared__ float smo[];
    float* Wcs = smo;               // [200][32]
    float* xs  = smo + 2 * D * 32;  // [32][200]

    int tid = threadIdx.x;
    int bt  = blockIdx.x;
    int gt  = bt >> 2, ct = bt & 3;
    int gbase = gt * 32;
    int cbase = ct * 32;

    for (int i = tid; i < 2 * D * 32; i += 256)
        Wcs[i] = g_Wcp[(i >> 5) * NP + cbase + (i & 31)];
    for (int q = tid; q < 32 * (2 * D / 4); q += 256)    // 1600 float4, coalesced
        reinterpret_cast<float4*>(xs)[q] =
            reinterpret_cast<const float4*>(g_wx)[gbase * (2 * D / 4) + q];
    __syncthreads();

    int gl = tid >> 3, hq = tid & 7;
    int h0 = hq * 4;
    int hglob = cbase + h0;
    const float* xr = &xs[gl * 2 * D];

    float4 acc = *reinterpret_cast<const float4*>(&g_bp[hglob]);
    #pragma unroll 4
    for (int k = 0; k < 2 * D; ++k) {
        float  xv = xr[k];                                    // 4-addr bcast
        float4 w  = *reinterpret_cast<const float4*>(&Wcs[k * 32 + h0]);
        acc.x = fmaf(xv, w.x, acc.x); acc.y = fmaf(xv, w.y, acc.y);
        acc.z = fmaf(xv, w.z, acc.z); acc.w = fmaf(xv, w.w, acc.w);
    }
    if (hglob < H)
        *reinterpret_cast<float4*>(&out[(gbase + gl) * H + hglob]) = acc;
}

// ---------------------------------------------------------------------------
extern "C" void kernel_launch(void* const* d_in, const int* in_sizes, int n_in,
                              void* d_out, int out_size) {
    const int*   nid = (const int*)d_in[0];
    const int*   adj = (const int*)d_in[1];
    const float* emb = (const float*)d_in[2];
    const float* Wq  = (const float*)d_in[3];
    const float* bq  = (const float*)d_in[4];
    const float* Wk  = (const float*)d_in[5];
    // d_in[6] = bk: cancels in softmax (constant per-row shift)
    const float* Wv  = (const float*)d_in[7];
    const float* bv  = (const float*)d_in[8];
    const float* Ws  = (const float*)d_in[9];
    const float* bs  = (const float*)d_in[10];
    float* out = (float*)d_out;

    const int smemO = (2 * D * 32 + 32 * 2 * D) * (int)sizeof(float);  // 51.2KB
    cudaFuncSetAttribute(k_out, cudaFuncAttributeMaxDynamicSharedMemorySize, smemO);

    k_pre<<<3 * D, 128>>>(Wq, bq, Wk, Wv, bv, Ws, bs);
    k_u<<<400, 256>>>(nid, emb);
    k_attn<<<NG, 128>>>(nid, adj, emb);
    k_out<<<400, 256, smemO>>>(out);
}

// round 10
// speedup vs baseline: 3.6528x; 1.0731x over previous
#include <cuda_runtime.h>
#include <math.h>

#define NG  3200   // graphs = B*L
#define E   50     // nodes per graph
#define D   100    // embedding dim
#define H   100    // head dim

// Scratch (no allocation allowed in kernel_launch)
__device__ __align__(16) float g_A[D * D];       // A: u[d] = sum_e x0[e]*g_A[e*D+d]
__device__ __align__(16) float g_cp[128];        // Wk @ bq, zero-padded to 128
__device__ __align__(16) float g_bp[128];        // bv + bs, zero-padded to 128
__device__ __align__(16) float g_U[NG * D];      // per-graph u
__device__ __align__(16) float g_wx[NG * 2 * D]; // per-graph packed [w(100) | x0(100)]

// ---------------------------------------------------------------------------
// K1: A = Wk Wq^T (row e per block), block 0 also c = Wk bq and bvs = bv+bs.
// grid = 100 x 128.  Wk staged in smem coalesced (pad-101).
// ---------------------------------------------------------------------------
__global__ void k_pre(const float* __restrict__ Wq, const float* __restrict__ bq,
                      const float* __restrict__ Wk,
                      const float* __restrict__ bv, const float* __restrict__ bs) {
    int b = blockIdx.x, t = threadIdx.x;
    __shared__ float wk[D * 101];   // 40.4KB, pad-101 -> conflict-free rows
    __shared__ float wq[H];
    __shared__ float bqs[H];
    if (t < H) wq[t] = Wq[b * H + t];
    if (b == 0 && t < H) bqs[t] = bq[t];
    for (int i = t; i < D * H; i += 128) {
        int r = i / H, cc = i - r * H;
        wk[r * 101 + cc] = Wk[i];
    }
    __syncthreads();
    if (t < D) {
        float acc = 0.f;
        #pragma unroll 4
        for (int h = 0; h < H; ++h) acc = fmaf(wk[t * 101 + h], wq[h], acc);
        g_A[b * D + t] = acc;
    }
    if (b == 0) {
        float c = 0.f, bb = 0.f;
        if (t < D) {
            #pragma unroll 4
            for (int h = 0; h < H; ++h) c = fmaf(wk[t * 101 + h], bqs[h], c);
            bb = bv[t] + bs[t];
        }
        g_cp[t] = c;   // t in [100,128): zero pad
        g_bp[t] = bb;
    }
}

// ---------------------------------------------------------------------------
// K2: U[g] = c + A x0[g].  CTA = 32 graphs x 32 cols, 128 thr, grid 400.
// Thread = 2 graphs x 4 cols: each weight LDS.128 feeds 8 FMAs.
// ---------------------------------------------------------------------------
__global__ __launch_bounds__(128) void k_u(const int* __restrict__ nid,
                                           const float* __restrict__ emb) {
    __shared__ float As[D * 32];    // [k][c] 12.8KB
    __shared__ float xs[32 * D];    // [g][k] 12.8KB
    __shared__ int ids[32];

    int tid = threadIdx.x;
    int bt = blockIdx.x, gt = bt >> 2, ct = bt & 3;
    int gbase = gt * 32, cbase = ct * 32;

    for (int i = tid; i < D * 32; i += 128) {
        int k = i >> 5, col = cbase + (i & 31);
        As[i] = (col < D) ? g_A[k * D + col] : 0.f;
    }
    if (tid < 32) ids[tid] = nid[(gbase + tid) * E];
    __syncthreads();
    for (int q = tid; q < 32 * (D / 4); q += 128) {      // 800 float4
        int r = q / 25, c = q % 25;
        reinterpret_cast<float4*>(&xs[r * D])[c] =
            reinterpret_cast<const float4*>(emb)[ids[r] * (D / 4) + c];
    }
    __syncthreads();

    int hq = tid & 7, h0 = hq * 4;
    int g0 = (tid >> 3) * 2;
    int hglob = cbase + h0;
    const float* x0r = &xs[g0 * D];
    const float* x1r = x0r + D;

    float4 a0 = *reinterpret_cast<const float4*>(&g_cp[hglob]);
    float4 a1 = a0;
    #pragma unroll 4
    for (int k = 0; k < D; ++k) {
        float4 w = *reinterpret_cast<const float4*>(&As[k * 32 + h0]);
        float xa = x0r[k], xb = x1r[k];
        a0.x = fmaf(xa, w.x, a0.x); a0.y = fmaf(xa, w.y, a0.y);
        a0.z = fmaf(xa, w.z, a0.z); a0.w = fmaf(xa, w.w, a0.w);
        a1.x = fmaf(xb, w.x, a1.x); a1.y = fmaf(xb, w.y, a1.y);
        a1.z = fmaf(xb, w.z, a1.z); a1.w = fmaf(xb, w.w, a1.w);
    }
    if (hglob < H) {
        *reinterpret_cast<float4*>(&g_U[(gbase + g0) * D + hglob]) = a0;
        *reinterpret_cast<float4*>(&g_U[(gbase + g0 + 1) * D + hglob]) = a1;
    }
}

// ---------------------------------------------------------------------------
// K3: per-graph attention, parallel ballot compaction. 1 CTA/graph, 128 thr.
// ---------------------------------------------------------------------------
__global__ __launch_bounds__(128) void k_attn(const int* __restrict__ nid,
                                              const int* __restrict__ adj,
                                              const float* __restrict__ emb) {
    constexpr int LD = 101;
    __shared__ float X[E * LD];
    __shared__ float u_s[D];
    __shared__ float sc[E];
    __shared__ float ps[E];
    __shared__ int ids[E];
    __shared__ unsigned bal[2];
    __shared__ int cnt_s;

    int g = blockIdx.x, tid = threadIdx.x;
    int warp = tid >> 5, lane = tid & 31;

    int myid = 0, m = 0;
    if (tid < E) {
        myid = nid[g * E + tid];
        m    = adj[g * (E * E) + tid * E];   // edge j -> node 0
    }
    if (tid < D) u_s[tid] = g_U[g * D + tid];

    unsigned bw = __ballot_sync(0xffffffffu, m != 0);
    if (warp < 2 && lane == 0) bal[warp] = bw;
    __syncthreads();
    unsigned b0 = bal[0], b1 = bal[1];
    int cnt = __popc(b0) + __popc(b1);
    if (tid == 0) cnt_s = cnt;
    if (tid < E && m) {
        int pos = __popc((warp ? b0 : 0u)) +
                  __popc((warp ? b1 : b0) & ((1u << lane) - 1u));
        ids[pos] = myid;
    }
    __syncthreads();
    cnt = cnt_s;

    for (int q = tid; q < cnt * (D / 4); q += 128) {
        int r = q / 25, cc = q % 25;
        float4 v = reinterpret_cast<const float4*>(emb)[ids[r] * (D / 4) + cc];
        float* dst = &X[r * LD + cc * 4];
        dst[0] = v.x; dst[1] = v.y; dst[2] = v.z; dst[3] = v.w;
    }
    __syncthreads();

    if (tid < cnt) {
        const float* xr = &X[tid * LD];
        float s0 = 0.f, s1 = 0.f;
        #pragma unroll 10
        for (int d2 = 0; d2 < D; d2 += 2) {
            s0 = fmaf(xr[d2],     u_s[d2],     s0);
            s1 = fmaf(xr[d2 + 1], u_s[d2 + 1], s1);
        }
        sc[tid] = (s0 + s1) * 0.1f;          // /sqrt(H)
    }
    __syncthreads();

    float mx = -1e30f;
    for (int j = 0; j < cnt; ++j) mx = fmaxf(mx, sc[j]);
    if (tid < cnt) ps[tid] = __expf(sc[tid] - mx);
    __syncthreads();

    float S = 0.f;
    for (int j = 0; j < cnt; ++j) S += ps[j];
    float inv = 1.0f / S;

    if (tid < D) {
        float w = 0.f;
        for (int j = 0; j < cnt; ++j) w = fmaf(ps[j], X[j * LD + tid], w);
        g_wx[g * (2 * D) + tid]     = w * inv;
        g_wx[g * (2 * D) + D + tid] = X[tid];   // compact row 0 = x0
    }
}

// ---------------------------------------------------------------------------
// K4: out[g] = bvs + [w|x0] @ [Wv;Ws].  CTA = 32 g x 32 c, 128 thr, grid 400.
// Thread = 2 graphs x 4 cols.  Wc slice staged straight from Wv/Ws (float4).
// ---------------------------------------------------------------------------
__global__ __launch_bounds__(128) void k_out(const float* __restrict__ Wv,
                                             const float* __restrict__ Ws,
                                             float* __restrict__ out) {
    extern __shared__ float smo[];
    float* Wcs = smo;               // [200][32] 25.6KB
    float* xs  = smo + 2 * D * 32;  // [32][200] 25.6KB

    int tid = threadIdx.x;
    int bt = blockIdx.x, gt = bt >> 2, ct = bt & 3;
    int gbase = gt * 32, cbase = ct * 32;

    for (int i4 = tid; i4 < 2 * D * 8; i4 += 128) {      // 1600 float4
        int k = i4 >> 3, col = cbase + (i4 & 7) * 4;
        float4 v = make_float4(0.f, 0.f, 0.f, 0.f);
        if (col < H) {
            const float* src = (k < D) ? &Wv[k * H + col] : &Ws[(k - D) * H + col];
            v = *reinterpret_cast<const float4*>(src);
        }
        *reinterpret_cast<float4*>(&Wcs[k * 32 + (i4 & 7) * 4]) = v;
    }
    for (int q = tid; q < 32 * (2 * D / 4); q += 128)    // 1600 float4, coalesced
        reinterpret_cast<float4*>(xs)[q] =
            reinterpret_cast<const float4*>(g_wx)[gbase * (2 * D / 4) + q];
    __syncthreads();

    int hq = tid & 7, h0 = hq * 4;
    int g0 = (tid >> 3) * 2;
    int hglob = cbase + h0;
    const float* x0r = &xs[g0 * 2 * D];
    const float* x1r = x0r + 2 * D;

    float4 a0 = *reinterpret_cast<const float4*>(&g_bp[hglob]);
    float4 a1 = a0;
    #pragma unroll 4
    for (int k = 0; k < 2 * D; ++k) {
        float4 w = *reinterpret_cast<const float4*>(&Wcs[k * 32 + h0]);
        float xa = x0r[k], xb = x1r[k];
        a0.x = fmaf(xa, w.x, a0.x); a0.y = fmaf(xa, w.y, a0.y);
        a0.z = fmaf(xa, w.z, a0.z); a0.w = fmaf(xa, w.w, a0.w);
        a1.x = fmaf(xb, w.x, a1.x); a1.y = fmaf(xb, w.y, a1.y);
        a1.z = fmaf(xb, w.z, a1.z); a1.w = fmaf(xb, w.w, a1.w);
    }
    if (hglob < H) {
        *reinterpret_cast<float4*>(&out[(gbase + g0) * H + hglob]) = a0;
        *reinterpret_cast<float4*>(&out[(gbase + g0 + 1) * H + hglob]) = a1;
    }
}

// ---------------------------------------------------------------------------
extern "C" void kernel_launch(void* const* d_in, const int* in_sizes, int n_in,
                              void* d_out, int out_size) {
    const int*   nid = (const int*)d_in[0];
    const int*   adj = (const int*)d_in[1];
    const float* emb = (const float*)d_in[2];
    const float* Wq  = (const float*)d_in[3];
    const float* bq  = (const float*)d_in[4];
    const float* Wk  = (const float*)d_in[5];
    // d_in[6] = bk: cancels in softmax (constant per-row shift)
    const float* Wv  = (const float*)d_in[7];
    const float* bv  = (const float*)d_in[8];
    const float* Ws  = (const float*)d_in[9];
    const float* bs  = (const float*)d_in[10];
    float* out = (float*)d_out;

    const int smemO = (2 * D * 32 + 32 * 2 * D) * (int)sizeof(float);  // 51.2KB
    cudaFuncSetAttribute(k_out, cudaFuncAttributeMaxDynamicSharedMemorySize, smemO);

    k_pre<<<D, 128>>>(Wq, bq, Wk, bv, bs);
    k_u<<<400, 128>>>(nid, emb);
    k_attn<<<NG, 128>>>(nid, adj, emb);
    k_out<<<400, 128, smemO>>>(Wv, Ws, out);
}